// round 2
// baseline (speedup 1.0000x reference)
#include <cuda_runtime.h>

#define NB 64
#define NN 512
#define NF 64

// Scratch (device globals; no allocation allowed in kernel_launch)
__device__ float g_XW[NB * NN * NF];   // 8 MB
__device__ float g_P [NB * NN * NF];   // 8 MB
__device__ float g_r [NB * NN];        // 128 KB
__device__ float g_cs[NF];
__device__ int   g_N [NB];

// ---------------------------------------------------------------------------
// col_sum[f] = sum_i a[i][f]; also decode N robustly (int32 vs int64 storage).
__global__ void k_colsum(const float* __restrict__ a, const int* __restrict__ N32) {
    const int f = threadIdx.x;  // 64 threads
    float s = 0.f;
#pragma unroll
    for (int i = 0; i < NF; i++) s += a[i * NF + f];
    g_cs[f] = s;

    // N dtype detection: values are in [1, 512]. If stored as int64 (LE), the
    // odd int32 words (hi halves) are all 0. If stored as int32, every odd
    // index holds N[odd] >= 1. Threads 0..31 probe odd words 1..63 (safe for
    // both layouts).
    __shared__ int odd_nz;
    if (f == 0) odd_nz = 0;
    __syncthreads();
    if (f < 32 && N32[2 * f + 1] != 0) atomicOr(&odd_nz, 1);
    __syncthreads();
    g_N[f] = odd_nz ? N32[f] : N32[2 * f];
}

// ---------------------------------------------------------------------------
// XW[r][d] = sum_c X[r][c] * W[c][d], r in [0, NB*NN)
__global__ __launch_bounds__(256) void k_xw(const float* __restrict__ X,
                                            const float* __restrict__ W) {
    __shared__ float Ws[NF][NF];
    __shared__ float Xs[64][NF + 1];
    const int r0 = blockIdx.x * 64;
    const int t = threadIdx.x;
    for (int i = t; i < NF * NF; i += 256) Ws[i / NF][i % NF] = W[i];
    for (int i = t; i < 64 * NF; i += 256)
        Xs[i / NF][i % NF] = X[(size_t)(r0 + i / NF) * NF + (i % NF)];
    __syncthreads();
    const int tx = t & 15, ty = t >> 4;
    float acc[4][4] = {};
    for (int c = 0; c < NF; c++) {
        float xv[4], wv[4];
#pragma unroll
        for (int ii = 0; ii < 4; ii++) xv[ii] = Xs[ty * 4 + ii][c];
#pragma unroll
        for (int jj = 0; jj < 4; jj++) wv[jj] = Ws[c][tx * 4 + jj];
#pragma unroll
        for (int ii = 0; ii < 4; ii++)
#pragma unroll
            for (int jj = 0; jj < 4; jj++) acc[ii][jj] += xv[ii] * wv[jj];
    }
#pragma unroll
    for (int ii = 0; ii < 4; ii++)
#pragma unroll
        for (int jj = 0; jj < 4; jj++)
            g_XW[(size_t)(r0 + ty * 4 + ii) * NF + tx * 4 + jj] = acc[ii][jj];
}

// ---------------------------------------------------------------------------
// P[b][i][f] = sum_j A[b][i][j]*Y[j][f]  +  (i<N[b] ? Y[i][f] : 0),  Y = XW * cs
// r[b][i]    = sum_j A[b][i][j] + (i<N[b] ? 1 : 0)
__global__ __launch_bounds__(256) void k_p(const float* __restrict__ Ag) {
    const int b = blockIdx.y;
    const int i0 = blockIdx.x * 64;
    __shared__ float As[64][33];
    __shared__ float Ys[32][NF];
    __shared__ float cs[NF];
    const int t = threadIdx.x;
    const int tx = t & 15, ty = t >> 4;
    if (t < NF) cs[t] = g_cs[t];
    __syncthreads();

    const float* Ab  = Ag   + (size_t)b * NN * NN;
    const float* XWb = g_XW + (size_t)b * NN * NF;

    float acc[4][4] = {};
    float rsum = 0.f;

    for (int j0 = 0; j0 < NN; j0 += 32) {
        for (int idx = t; idx < 64 * 32; idx += 256) {
            int rr = idx >> 5, cc = idx & 31;
            As[rr][cc] = Ab[(size_t)(i0 + rr) * NN + j0 + cc];
        }
        for (int idx = t; idx < 32 * NF; idx += 256) {
            int rr = idx / NF, cc = idx % NF;
            Ys[rr][cc] = XWb[(size_t)(j0 + rr) * NF + cc] * cs[cc];
        }
        __syncthreads();
        if (t < 64) {
#pragma unroll
            for (int cc = 0; cc < 32; cc++) rsum += As[t][cc];
        }
#pragma unroll 8
        for (int jj = 0; jj < 32; jj++) {
            float av[4], yv[4];
#pragma unroll
            for (int ii = 0; ii < 4; ii++) av[ii] = As[ty * 4 + ii][jj];
#pragma unroll
            for (int cc = 0; cc < 4; cc++) yv[cc] = Ys[jj][tx * 4 + cc];
#pragma unroll
            for (int ii = 0; ii < 4; ii++)
#pragma unroll
                for (int cc = 0; cc < 4; cc++) acc[ii][cc] += av[ii] * yv[cc];
        }
        __syncthreads();
    }

    const int nb = g_N[b];
#pragma unroll
    for (int ii = 0; ii < 4; ii++) {
        const int i = i0 + ty * 4 + ii;
        const bool self = (i < nb);
#pragma unroll
        for (int cc = 0; cc < 4; cc++) {
            const int f = tx * 4 + cc;
            float v = acc[ii][cc];
            if (self) v += XWb[(size_t)i * NF + f] * cs[f];
            g_P[((size_t)b * NN + i) * NF + f] = v;
        }
    }
    if (t < 64) {
        const int i = i0 + t;
        g_r[b * NN + i] = rsum + ((i < nb) ? 1.0f : 0.0f);
    }
}

// ---------------------------------------------------------------------------
// H[b][i][d] = sum_k tanh( P[i,:].XW[k,:] + r[i]*ba[k] ) * XW[k][d] + bW[d]
// Flash-style: att tile lives in smem only, never HBM.
__global__ __launch_bounds__(256) void k_fused(const float* __restrict__ bias_a,
                                               const float* __restrict__ bias_W,
                                               float* __restrict__ H) {
    const int b = blockIdx.y;
    const int i0 = blockIdx.x * 64;
    __shared__ float Ps [64][NF + 1];
    __shared__ float XWs[64][NF + 1];
    __shared__ float Ss [64][64 + 1];
    __shared__ float rs [64];
    __shared__ float bak[64];
    const int t = threadIdx.x;
    const int tx = t & 15, ty = t >> 4;

    const float* Pb  = g_P  + ((size_t)b * NN + i0) * NF;
    const float* XWb = g_XW + (size_t)b * NN * NF;

    for (int i = t; i < 64 * NF; i += 256) Ps[i / NF][i % NF] = Pb[i];
    if (t < 64) rs[t] = g_r[b * NN + i0 + t];

    float hacc[4][4] = {};

    for (int k0 = 0; k0 < NN; k0 += 64) {
        __syncthreads();  // protects XWs/Ss reuse + first-iter Ps/rs visibility
        for (int i = t; i < 64 * NF; i += 256)
            XWs[i / NF][i % NF] = XWb[(size_t)(k0 + i / NF) * NF + (i % NF)];
        if (t < 64) bak[t] = bias_a[k0 + t];
        __syncthreads();

        // S = tanh(P @ XW^T + r * ba)
        float sacc[4][4] = {};
#pragma unroll 8
        for (int f = 0; f < NF; f++) {
            float pv[4], xv[4];
#pragma unroll
            for (int ii = 0; ii < 4; ii++) pv[ii] = Ps[ty * 4 + ii][f];
#pragma unroll
            for (int kk = 0; kk < 4; kk++) xv[kk] = XWs[tx * 4 + kk][f];
#pragma unroll
            for (int ii = 0; ii < 4; ii++)
#pragma unroll
                for (int kk = 0; kk < 4; kk++) sacc[ii][kk] += pv[ii] * xv[kk];
        }
#pragma unroll
        for (int ii = 0; ii < 4; ii++)
#pragma unroll
            for (int kk = 0; kk < 4; kk++)
                Ss[ty * 4 + ii][tx * 4 + kk] =
                    tanhf(sacc[ii][kk] + rs[ty * 4 + ii] * bak[tx * 4 + kk]);
        __syncthreads();

        // H += S @ XW
#pragma unroll 8
        for (int kk = 0; kk < 64; kk++) {
            float sv[4], xv[4];
#pragma unroll
            for (int ii = 0; ii < 4; ii++) sv[ii] = Ss[ty * 4 + ii][kk];
#pragma unroll
            for (int dd = 0; dd < 4; dd++) xv[dd] = XWs[kk][tx * 4 + dd];
#pragma unroll
            for (int ii = 0; ii < 4; ii++)
#pragma unroll
                for (int dd = 0; dd < 4; dd++) hacc[ii][dd] += sv[ii] * xv[dd];
        }
    }

#pragma unroll
    for (int ii = 0; ii < 4; ii++)
#pragma unroll
        for (int dd = 0; dd < 4; dd++)
            H[((size_t)b * NN + i0 + ty * 4 + ii) * NF + tx * 4 + dd] =
                hacc[ii][dd] + bias_W[tx * 4 + dd];
}

// ---------------------------------------------------------------------------
extern "C" void kernel_launch(void* const* d_in, const int* in_sizes, int n_in,
                              void* d_out, int out_size) {
    const float* X  = (const float*)d_in[0];
    const float* A  = (const float*)d_in[1];
    const int*   N  = (const int*)d_in[2];   // robustly decoded in k_colsum
    const float* W  = (const float*)d_in[3];
    const float* a  = (const float*)d_in[4];
    const float* bW = (const float*)d_in[5];
    const float* ba = (const float*)d_in[6];
    float* H = (float*)d_out;

    k_colsum<<<1, NF>>>(a, N);
    k_xw<<<(NB * NN) / 64, 256>>>(X, W);
    k_p<<<dim3(NN / 64, NB), 256>>>(A);
    k_fused<<<dim3(NN / 64, NB), 256>>>(ba, bW, H);
}

// round 3
// speedup vs baseline: 1.2374x; 1.2374x over previous
#include <cuda_runtime.h>

#define NB 64
#define NN 512
#define NF 64

// Scratch (device globals; no allocation allowed in kernel_launch)
__device__ float g_XW[NB * NN * NF];   // 8 MB
__device__ float g_P [NB * NN * NF];   // 8 MB
__device__ float g_r [NB * NN];        // 128 KB
__device__ float g_cs[NF];
__device__ int   g_N [NB];

// ---------------- f32x2 helpers ----------------
typedef unsigned long long u64;

__device__ __forceinline__ u64 dup2(float x) {
    unsigned xi = __float_as_uint(x);
    u64 d;
    asm("mov.b64 %0, {%1, %1};" : "=l"(d) : "r"(xi));
    return d;
}
__device__ __forceinline__ u64 pack2(float lo, float hi) {
    unsigned a = __float_as_uint(lo), b = __float_as_uint(hi);
    u64 d;
    asm("mov.b64 %0, {%1, %2};" : "=l"(d) : "r"(a), "r"(b));
    return d;
}
__device__ __forceinline__ void unpack2(u64 d, float& lo, float& hi) {
    unsigned a, b;
    asm("mov.b64 {%0, %1}, %2;" : "=r"(a), "=r"(b) : "l"(d));
    lo = __uint_as_float(a);
    hi = __uint_as_float(b);
}
#define FMA2(acc, a, b) \
    asm("fma.rn.f32x2 %0, %1, %2, %0;" : "+l"(acc) : "l"(a), "l"(b))

__device__ __forceinline__ float tanh_fast(float x) {
    float y;
    asm("tanh.approx.f32 %0, %1;" : "=f"(y) : "f"(x));
    return y;
}

// ---------------------------------------------------------------------------
// col_sum[f] = sum_i a[i][f]; also decode N robustly (int32 vs int64 storage).
__global__ void k_colsum(const float* __restrict__ a, const int* __restrict__ N32) {
    const int f = threadIdx.x;  // 64 threads
    float s = 0.f;
#pragma unroll
    for (int i = 0; i < NF; i++) s += a[i * NF + f];
    g_cs[f] = s;

    __shared__ int odd_nz;
    if (f == 0) odd_nz = 0;
    __syncthreads();
    if (f < 32 && N32[2 * f + 1] != 0) atomicOr(&odd_nz, 1);
    __syncthreads();
    g_N[f] = odd_nz ? N32[f] : N32[2 * f];
}

// ---------------------------------------------------------------------------
// XW[r][d] = sum_c X[r][c] * W[c][d]   (small: 0.13 GF)
__global__ __launch_bounds__(256) void k_xw(const float* __restrict__ X,
                                            const float* __restrict__ W) {
    __shared__ __align__(16) float Ws[NF][NF];
    __shared__ __align__(16) float Xs[64][NF + 4];
    const int r0 = blockIdx.x * 64;
    const int t = threadIdx.x;
    for (int i = t; i < NF * NF; i += 256) Ws[i / NF][i % NF] = W[i];
    for (int i = t; i < 64 * NF; i += 256)
        Xs[i / NF][i % NF] = X[(size_t)(r0 + i / NF) * NF + (i % NF)];
    __syncthreads();
    const int tx = t & 15, ty = t >> 4;
    float acc[4][4] = {};
    for (int c = 0; c < NF; c++) {
        float xv[4], wv[4];
#pragma unroll
        for (int ii = 0; ii < 4; ii++) xv[ii] = Xs[ty * 4 + ii][c];
#pragma unroll
        for (int jj = 0; jj < 4; jj++) wv[jj] = Ws[c][tx * 4 + jj];
#pragma unroll
        for (int ii = 0; ii < 4; ii++)
#pragma unroll
            for (int jj = 0; jj < 4; jj++) acc[ii][jj] += xv[ii] * wv[jj];
    }
#pragma unroll
    for (int ii = 0; ii < 4; ii++)
#pragma unroll
        for (int jj = 0; jj < 4; jj++)
            g_XW[(size_t)(r0 + ty * 4 + ii) * NF + tx * 4 + jj] = acc[ii][jj];
}

// ---------------------------------------------------------------------------
// P[b][i][f] = sum_j A[b][i][j]*Y[j][f] + (i<N[b] ? Y[i][f] : 0),  Y = XW*cs
// r[b][i]    = sum_j A[b][i][j] + (i<N[b] ? 1 : 0)
// 64x64 tile per block, f32x2 inner, all smem reads LDS.128.
__global__ __launch_bounds__(256) void k_p(const float* __restrict__ Ag) {
    const int b = blockIdx.y;
    const int i0 = blockIdx.x * 64;
    __shared__ __align__(16) float AsT[64][68];  // AsT[j][i]
    __shared__ __align__(16) float Ys [64][68];  // Ys[j][f] (already *cs)
    __shared__ __align__(16) float csv[NF];
    const int t = threadIdx.x;
    const int tx = t & 15, ty = t >> 4;
    if (t < NF) csv[t] = g_cs[t];
    __syncthreads();

    const float*  Ab   = Ag + (size_t)b * NN * NN;
    const float4* XWb4 = (const float4*)(g_XW + (size_t)b * NN * NF);

    u64 acc2[4][2] = {};
    float rsum = 0.f;

    for (int j0 = 0; j0 < NN; j0 += 64) {
        __syncthreads();
        // A tile -> AsT (transposed), coalesced float4 global reads
        for (int q = t; q < 64 * 16; q += 256) {
            int r = q >> 4, c4 = q & 15;
            float4 v = *(const float4*)&Ab[(size_t)(i0 + r) * NN + j0 + c4 * 4];
            AsT[c4 * 4 + 0][r] = v.x;
            AsT[c4 * 4 + 1][r] = v.y;
            AsT[c4 * 4 + 2][r] = v.z;
            AsT[c4 * 4 + 3][r] = v.w;
        }
        // Y tile = XW*cs, row-major float4
        for (int q = t; q < 64 * 16; q += 256) {
            int j = q >> 4, f4 = q & 15;
            float4 v = XWb4[(size_t)(j0 + j) * 16 + f4];
            float4 c = *(const float4*)&csv[f4 * 4];
            v.x *= c.x; v.y *= c.y; v.z *= c.z; v.w *= c.w;
            *(float4*)&Ys[j][f4 * 4] = v;
        }
        __syncthreads();

        if (t < 64) {
#pragma unroll 8
            for (int jj = 0; jj < 64; jj++) rsum += AsT[jj][t];
        }

#pragma unroll 8
        for (int jj = 0; jj < 64; jj++) {
            float4 av = *(float4*)&AsT[jj][ty * 4];
            float4 yv = *(float4*)&Ys[jj][tx * 4];
            u64 y01 = pack2(yv.x, yv.y);
            u64 y23 = pack2(yv.z, yv.w);
            u64 a0 = dup2(av.x), a1 = dup2(av.y), a2 = dup2(av.z), a3 = dup2(av.w);
            FMA2(acc2[0][0], a0, y01); FMA2(acc2[0][1], a0, y23);
            FMA2(acc2[1][0], a1, y01); FMA2(acc2[1][1], a1, y23);
            FMA2(acc2[2][0], a2, y01); FMA2(acc2[2][1], a2, y23);
            FMA2(acc2[3][0], a3, y01); FMA2(acc2[3][1], a3, y23);
        }
    }

    const int nb = g_N[b];
    const float4 c4v = *(const float4*)&csv[tx * 4];
#pragma unroll
    for (int ii = 0; ii < 4; ii++) {
        const int i = i0 + ty * 4 + ii;
        float4 o;
        unpack2(acc2[ii][0], o.x, o.y);
        unpack2(acc2[ii][1], o.z, o.w);
        if (i < nb) {
            float4 xw = XWb4[(size_t)i * 16 + tx];
            o.x += xw.x * c4v.x; o.y += xw.y * c4v.y;
            o.z += xw.z * c4v.z; o.w += xw.w * c4v.w;
        }
        *(float4*)&g_P[((size_t)b * NN + i) * NF + tx * 4] = o;
    }
    if (t < 64) {
        const int i = i0 + t;
        g_r[b * NN + i] = rsum + ((i < nb) ? 1.0f : 0.0f);
    }
}

// ---------------------------------------------------------------------------
// k_fused: H[i][d] = sum_k tanh(P[i,:].XW[k,:] + r[i]*ba[k]) * XW[k][d] + bW[d]
// i-tile = 128, 256 threads, 8x4 thread tile, f32x2 + LDS.128 everywhere.
#define IT 128
// dynamic smem layout (floats):
#define OFF_PST  0                         // PsT[64][IT+4]
#define OFF_XWS  (OFF_PST + 64 * (IT + 4)) // XWs[64][68]
#define OFF_XWT  (OFF_XWS + 64 * 68)       // XWT[64][68]
#define OFF_SST  (OFF_XWT + 64 * 68)       // SsT[64][IT+4]
#define OFF_RS   (OFF_SST + 64 * (IT + 4)) // rs[IT]
#define OFF_BAK  (OFF_RS + IT)             // bak[64]
#define SMEM_FLT (OFF_BAK + 64)

__global__ __launch_bounds__(256, 2) void k_fused(const float* __restrict__ bias_a,
                                                  const float* __restrict__ bias_W,
                                                  float* __restrict__ H) {
    extern __shared__ __align__(16) float dsm[];
    float* PsT = dsm + OFF_PST;   // [f][i], stride IT+4
    float* XWs = dsm + OFF_XWS;   // [k][d], stride 68
    float* XWT = dsm + OFF_XWT;   // [f][k], stride 68
    float* SsT = dsm + OFF_SST;   // [k][i], stride IT+4
    float* rs  = dsm + OFF_RS;
    float* bak = dsm + OFF_BAK;
    const int PST = IT + 4;

    const int b  = blockIdx.y;
    const int i0 = blockIdx.x * IT;
    const int t  = threadIdx.x;
    const int tx = t & 15, ty = t >> 4;  // tx*4 = col, ty*8 = row

    const float4* Pb4  = (const float4*)(g_P  + ((size_t)b * NN + i0) * NF);
    const float4* XWb4 = (const float4*)(g_XW + (size_t)b * NN * NF);

    // Load P tile transposed
    for (int q = t; q < IT * 16; q += 256) {
        int i = q >> 4, f4 = q & 15;
        float4 v = Pb4[i * 16 + f4];
        PsT[(f4 * 4 + 0) * PST + i] = v.x;
        PsT[(f4 * 4 + 1) * PST + i] = v.y;
        PsT[(f4 * 4 + 2) * PST + i] = v.z;
        PsT[(f4 * 4 + 3) * PST + i] = v.w;
    }
    if (t < IT) rs[t] = g_r[b * NN + i0 + t];

    u64 hacc2[8][2] = {};
    float rv[8];

    for (int k0 = 0; k0 < NN; k0 += 64) {
        __syncthreads();  // prev-iter consumers done; also fences initial loads
        for (int q = t; q < 64 * 16; q += 256) {
            int k = q >> 4, f4 = q & 15;
            float4 v = XWb4[(size_t)(k0 + k) * 16 + f4];
            *(float4*)&XWs[k * 68 + f4 * 4] = v;
            XWT[(f4 * 4 + 0) * 68 + k] = v.x;
            XWT[(f4 * 4 + 1) * 68 + k] = v.y;
            XWT[(f4 * 4 + 2) * 68 + k] = v.z;
            XWT[(f4 * 4 + 3) * 68 + k] = v.w;
        }
        if (t < 64) bak[t] = bias_a[k0 + t];
        __syncthreads();

        // ---- S = tanh(P @ XW^T + r*ba), stored transposed SsT[k][i] ----
        u64 sacc2[8][2] = {};
#pragma unroll 8
        for (int f = 0; f < NF; f++) {
            float4 p0 = *(float4*)&PsT[f * PST + ty * 8];
            float4 p1 = *(float4*)&PsT[f * PST + ty * 8 + 4];
            float4 xv = *(float4*)&XWT[f * 68 + tx * 4];
            u64 x01 = pack2(xv.x, xv.y);
            u64 x23 = pack2(xv.z, xv.w);
            u64 d0 = dup2(p0.x), d1 = dup2(p0.y), d2 = dup2(p0.z), d3 = dup2(p0.w);
            u64 d4 = dup2(p1.x), d5 = dup2(p1.y), d6 = dup2(p1.z), d7 = dup2(p1.w);
            FMA2(sacc2[0][0], d0, x01); FMA2(sacc2[0][1], d0, x23);
            FMA2(sacc2[1][0], d1, x01); FMA2(sacc2[1][1], d1, x23);
            FMA2(sacc2[2][0], d2, x01); FMA2(sacc2[2][1], d2, x23);
            FMA2(sacc2[3][0], d3, x01); FMA2(sacc2[3][1], d3, x23);
            FMA2(sacc2[4][0], d4, x01); FMA2(sacc2[4][1], d4, x23);
            FMA2(sacc2[5][0], d5, x01); FMA2(sacc2[5][1], d5, x23);
            FMA2(sacc2[6][0], d6, x01); FMA2(sacc2[6][1], d6, x23);
            FMA2(sacc2[7][0], d7, x01); FMA2(sacc2[7][1], d7, x23);
        }
        float s[8][4];
#pragma unroll
        for (int ii = 0; ii < 8; ii++) {
            unpack2(sacc2[ii][0], s[ii][0], s[ii][1]);
            unpack2(sacc2[ii][1], s[ii][2], s[ii][3]);
        }
#pragma unroll
        for (int ii = 0; ii < 8; ii++) rv[ii] = rs[ty * 8 + ii];
#pragma unroll
        for (int kk = 0; kk < 4; kk++) {
            const int k = tx * 4 + kk;
            const float bv = bak[k];
            float4 w0, w1;
            w0.x = tanh_fast(s[0][kk] + rv[0] * bv);
            w0.y = tanh_fast(s[1][kk] + rv[1] * bv);
            w0.z = tanh_fast(s[2][kk] + rv[2] * bv);
            w0.w = tanh_fast(s[3][kk] + rv[3] * bv);
            w1.x = tanh_fast(s[4][kk] + rv[4] * bv);
            w1.y = tanh_fast(s[5][kk] + rv[5] * bv);
            w1.z = tanh_fast(s[6][kk] + rv[6] * bv);
            w1.w = tanh_fast(s[7][kk] + rv[7] * bv);
            *(float4*)&SsT[k * PST + ty * 8]     = w0;
            *(float4*)&SsT[k * PST + ty * 8 + 4] = w1;
        }
        __syncthreads();

        // ---- H += S @ XW ----
#pragma unroll 8
        for (int kk = 0; kk < 64; kk++) {
            float4 s0 = *(float4*)&SsT[kk * PST + ty * 8];
            float4 s1 = *(float4*)&SsT[kk * PST + ty * 8 + 4];
            float4 xv = *(float4*)&XWs[kk * 68 + tx * 4];
            u64 x01 = pack2(xv.x, xv.y);
            u64 x23 = pack2(xv.z, xv.w);
            u64 d0 = dup2(s0.x), d1 = dup2(s0.y), d2 = dup2(s0.z), d3 = dup2(s0.w);
            u64 d4 = dup2(s1.x), d5 = dup2(s1.y), d6 = dup2(s1.z), d7 = dup2(s1.w);
            FMA2(hacc2[0][0], d0, x01); FMA2(hacc2[0][1], d0, x23);
            FMA2(hacc2[1][0], d1, x01); FMA2(hacc2[1][1], d1, x23);
            FMA2(hacc2[2][0], d2, x01); FMA2(hacc2[2][1], d2, x23);
            FMA2(hacc2[3][0], d3, x01); FMA2(hacc2[3][1], d3, x23);
            FMA2(hacc2[4][0], d4, x01); FMA2(hacc2[4][1], d4, x23);
            FMA2(hacc2[5][0], d5, x01); FMA2(hacc2[5][1], d5, x23);
            FMA2(hacc2[6][0], d6, x01); FMA2(hacc2[6][1], d6, x23);
            FMA2(hacc2[7][0], d7, x01); FMA2(hacc2[7][1], d7, x23);
        }
    }

    const float4 bw = *(const float4*)&bias_W[tx * 4];
#pragma unroll
    for (int ii = 0; ii < 8; ii++) {
        float4 o;
        unpack2(hacc2[ii][0], o.x, o.y);
        unpack2(hacc2[ii][1], o.z, o.w);
        o.x += bw.x; o.y += bw.y; o.z += bw.z; o.w += bw.w;
        *(float4*)&H[((size_t)b * NN + i0 + ty * 8 + ii) * NF + tx * 4] = o;
    }
}

// ---------------------------------------------------------------------------
extern "C" void kernel_launch(void* const* d_in, const int* in_sizes, int n_in,
                              void* d_out, int out_size) {
    const float* X  = (const float*)d_in[0];
    const float* A  = (const float*)d_in[1];
    const int*   N  = (const int*)d_in[2];   // robustly decoded in k_colsum
    const float* W  = (const float*)d_in[3];
    const float* a  = (const float*)d_in[4];
    const float* bW = (const float*)d_in[5];
    const float* ba = (const float*)d_in[6];
    float* H = (float*)d_out;

    cudaFuncSetAttribute(k_fused, cudaFuncAttributeMaxDynamicSharedMemorySize,
                         SMEM_FLT * (int)sizeof(float));

    k_colsum<<<1, NF>>>(a, N);
    k_xw<<<(NB * NN) / 64, 256>>>(X, W);
    k_p<<<dim3(NN / 64, NB), 256>>>(A);
    k_fused<<<dim3(NN / IT, NB), 256, SMEM_FLT * sizeof(float)>>>(ba, bW, H);
}